// round 6
// baseline (speedup 1.0000x reference)
#include <cuda_runtime.h>
#include <cuda_bf16.h>
#include <math.h>

#define BB 64
#define CC 1024
#define QQ 256
#define DD 128
#define OUTD (4*DD)
#define NEGV (-1e30f)
#define NCHUNK 16

// smem leading dims (bf16 elements)
#define AS_LD 40     // 32 + 8 pad
#define BS_LD 136    // 128 + 8 pad (k3/k4)
#define BS_LD1 264   // 256 + 8 pad (k1)

// ---- scratch (device globals: allocation-free) ----
__device__ float g_S[(size_t)BB*CC*QQ];      // final S (incl. s0+s1+bias), 64 MB
__device__ float g_s0[BB*CC];                // x_cont@W0 + bias
__device__ float g_s1[BB*QQ];                // x_ques@W1
__device__ float g_pm[BB*NCHUNK*QQ];
__device__ float g_ps[BB*NCHUNK*QQ];
__device__ float g_colM[BB*QQ];
__device__ float g_colZ[BB*QQ];
__device__ float g_rowM[BB*CC];
__device__ float g_rowZ[BB*CC];
__device__ float g_A[(size_t)BB*QQ*DD];      // S_T @ x_cont, 8 MB

// ---------------------------------------------------------------------------
// MMA helpers
// ---------------------------------------------------------------------------
__device__ __forceinline__ void mma16816(float* c, const unsigned* a, const unsigned* b)
{
    asm volatile(
        "mma.sync.aligned.m16n8k16.row.col.f32.bf16.bf16.f32 "
        "{%0,%1,%2,%3},{%4,%5,%6,%7},{%8,%9},{%0,%1,%2,%3};"
        : "+f"(c[0]), "+f"(c[1]), "+f"(c[2]), "+f"(c[3])
        : "r"(a[0]), "r"(a[1]), "r"(a[2]), "r"(a[3]), "r"(b[0]), "r"(b[1]));
}

__device__ __forceinline__ void ldsm4(unsigned* r, const __nv_bfloat16* p)
{
    unsigned addr = (unsigned)__cvta_generic_to_shared(p);
    asm volatile("ldmatrix.sync.aligned.m8n8.x4.shared.b16 {%0,%1,%2,%3},[%4];"
                 : "=r"(r[0]), "=r"(r[1]), "=r"(r[2]), "=r"(r[3]) : "r"(addr));
}

__device__ __forceinline__ void ldsm4t(unsigned* r, const __nv_bfloat16* p)
{
    unsigned addr = (unsigned)__cvta_generic_to_shared(p);
    asm volatile("ldmatrix.sync.aligned.m8n8.x4.trans.shared.b16 {%0,%1,%2,%3},[%4];"
                 : "=r"(r[0]), "=r"(r[1]), "=r"(r[2]), "=r"(r[3]) : "r"(addr));
}

__device__ __forceinline__ void split2(float x, __nv_bfloat16& h, __nv_bfloat16& l)
{
    h = __float2bfloat16(x);
    l = __float2bfloat16(x - __bfloat162float(h));
}

// load B-fragments (hi & lo) for a 64-wide n range at kstep ks; layout [K][ld]
__device__ __forceinline__ void load_bfrags(unsigned bh[8][2], unsigned bl[8][2],
                                            const __nv_bfloat16* Bh, const __nv_bfloat16* Bl,
                                            int ld, int ks, int wn, int lane)
{
    int brow = ks + (lane & 7) + ((lane & 16) ? 8 : 0);
#pragma unroll
    for (int g4 = 0; g4 < 4; g4++) {
        int bcol = wn + g4*16 + ((lane & 8) ? 8 : 0);
        unsigned t[4];
        ldsm4t(t, &Bh[brow*ld + bcol]);
        bh[2*g4][0] = t[0]; bh[2*g4][1] = t[2];
        bh[2*g4+1][0] = t[1]; bh[2*g4+1][1] = t[3];
        ldsm4t(t, &Bl[brow*ld + bcol]);
        bl[2*g4][0] = t[0]; bl[2*g4][1] = t[2];
        bl[2*g4+1][0] = t[1]; bl[2*g4+1][1] = t[3];
    }
}

// ---------------------------------------------------------------------------
// projections: s0 = x_cont @ W0 + bias, s1 = x_ques @ W1  (one warp per row)
// ---------------------------------------------------------------------------
__device__ __forceinline__ float row_dot(const float* __restrict__ xr,
                                         const float* __restrict__ W, int lane)
{
    float s = 0.f;
#pragma unroll
    for (int d = 0; d < DD; d += 32) s += xr[d + lane] * W[d + lane];
#pragma unroll
    for (int o = 16; o > 0; o >>= 1) s += __shfl_xor_sync(0xffffffffu, s, o);
    return s;
}

__global__ void k_s0(const float* __restrict__ x, const float* __restrict__ W,
                     const float* __restrict__ bias)
{
    int warp = (blockIdx.x * blockDim.x + threadIdx.x) >> 5;
    int lane = threadIdx.x & 31;
    if (warp >= BB*CC) return;
    float s = row_dot(x + (size_t)warp * DD, W, lane);
    if (lane == 0) g_s0[warp] = s + bias[0];
}

__global__ void k_s1(const float* __restrict__ x, const float* __restrict__ W)
{
    int warp = (blockIdx.x * blockDim.x + threadIdx.x) >> 5;
    int lane = threadIdx.x & 31;
    if (warp >= BB*QQ) return;
    float s = row_dot(x + (size_t)warp * DD, W, lane);
    if (lane == 0) g_s1[warp] = s;
}

// ---------------------------------------------------------------------------
// K1: S[b,c,q] = sum_d (xc*W2)[c,d]*xq[q,d] + s0 + s1, FUSED with
//     row softmax stats (exact) + per-block partial column stats.
// BLK 64c x 256q (full Q), 8 warps, warp tile 16x128.
// ---------------------------------------------------------------------------
__global__ __launch_bounds__(256) void k1_S(const float* __restrict__ xc,
                                            const float* __restrict__ xq,
                                            const float* __restrict__ W2,
                                            const float* __restrict__ cmask,
                                            const float* __restrict__ qmask)
{
    __shared__ __align__(16) char sbuf[44032];
    __nv_bfloat16* Ah = (__nv_bfloat16*)sbuf;                 // 64*AS_LD
    __nv_bfloat16* Al = Ah + 64*AS_LD;
    __nv_bfloat16* Bh = (__nv_bfloat16*)(sbuf + 10240);       // 32*BS_LD1
    __nv_bfloat16* Bl = Bh + 32*BS_LD1;
    // stats scratch aliases the (dead-after-mainloop) B region
    float* rmaxS = (float*)(sbuf + 10240);   // [64][2]
    float* rsumS = rmaxS + 128;              // [64][2]
    float* cmaxS = rsumS + 128;              // [256][4]
    float* csumS = cmaxS + 1024;             // [256][4]

    __shared__ float W2s[DD];
    __shared__ float s1s[QQ];
    __shared__ float qmn[QQ];
    __shared__ float cmn[64];

    int b  = blockIdx.z;
    int cb = blockIdx.y;
    int c0 = cb * 64;
    int tid = threadIdx.x;
    int warp = tid >> 5, lane = tid & 31;
    int warp_m = warp >> 1, warp_n = warp & 1;
    int wm = warp_m * 16, wn = warp_n * 128;

    if (tid < DD) W2s[tid] = W2[tid];
    s1s[tid] = g_s1[b*QQ + tid];
    qmn[tid] = NEGV * (1.f - qmask[b*QQ + tid]);
    if (tid < 64) cmn[tid] = NEGV * (1.f - cmask[b*CC + c0 + tid]);

    float acc[16][4] = {};
    __syncthreads();

    for (int k0 = 0; k0 < DD; k0 += 32) {
        // A tile: 64c x 32d, scaled by W2, hi/lo split
#pragma unroll
        for (int i = 0; i < 2; i++) {
            int f = tid + i*256;
            int r = f >> 3, c4 = (f & 7) * 4;
            float4 v = *(const float4*)&xc[((size_t)(b*CC + c0 + r))*DD + k0 + c4];
            float w0 = v.x * W2s[k0+c4+0], w1 = v.y * W2s[k0+c4+1];
            float w2v = v.z * W2s[k0+c4+2], w3 = v.w * W2s[k0+c4+3];
            __nv_bfloat16 h, l;
            split2(w0, h, l); Ah[r*AS_LD + c4+0] = h; Al[r*AS_LD + c4+0] = l;
            split2(w1, h, l); Ah[r*AS_LD + c4+1] = h; Al[r*AS_LD + c4+1] = l;
            split2(w2v,h, l); Ah[r*AS_LD + c4+2] = h; Al[r*AS_LD + c4+2] = l;
            split2(w3, h, l); Ah[r*AS_LD + c4+3] = h; Al[r*AS_LD + c4+3] = l;
        }
        // B tile: [k=d 32][n=q 256] = xq^T, hi/lo split
#pragma unroll
        for (int i = 0; i < 8; i++) {
            int f = tid + i*256;
            int q = f >> 3, d4 = (f & 7) * 4;
            float4 v = *(const float4*)&xq[((size_t)(b*QQ + q))*DD + k0 + d4];
            __nv_bfloat16 h, l;
            split2(v.x, h, l); Bh[(d4+0)*BS_LD1 + q] = h; Bl[(d4+0)*BS_LD1 + q] = l;
            split2(v.y, h, l); Bh[(d4+1)*BS_LD1 + q] = h; Bl[(d4+1)*BS_LD1 + q] = l;
            split2(v.z, h, l); Bh[(d4+2)*BS_LD1 + q] = h; Bl[(d4+2)*BS_LD1 + q] = l;
            split2(v.w, h, l); Bh[(d4+3)*BS_LD1 + q] = h; Bl[(d4+3)*BS_LD1 + q] = l;
        }
        __syncthreads();
#pragma unroll
        for (int ks = 0; ks < 32; ks += 16) {
            unsigned ah[4], al[4];
            int arow = wm + (lane & 15);
            int acol = ks + ((lane & 16) ? 8 : 0);
            ldsm4(ah, &Ah[arow*AS_LD + acol]);
            ldsm4(al, &Al[arow*AS_LD + acol]);
#pragma unroll
            for (int half = 0; half < 2; half++) {
                unsigned bh[8][2], bl[8][2];
                load_bfrags(bh, bl, Bh, Bl, BS_LD1, ks, wn + half*64, lane);
#pragma unroll
                for (int nj = 0; nj < 8; nj++) {
                    int j = half*8 + nj;
                    mma16816(acc[j], ah, bh[nj]);
                    mma16816(acc[j], ah, bl[nj]);
                    mma16816(acc[j], al, bh[nj]);
                }
            }
        }
        __syncthreads();   // tiles dead after this; stats scratch may alias
    }

    int g = lane >> 2, tg = lane & 3;
    int row0 = wm + g, row1 = wm + g + 8;

    // ---- finalize S (add s0 + s1) and store ----
    float s0a = g_s0[b*CC + c0 + row0];
    float s0b = g_s0[b*CC + c0 + row1];
#pragma unroll
    for (int nj = 0; nj < 16; nj++) {
        int q_ = wn + nj*8 + tg*2;
        float s1a = s1s[q_], s1b = s1s[q_+1];
        acc[nj][0] += s0a + s1a; acc[nj][1] += s0a + s1b;
        acc[nj][2] += s0b + s1a; acc[nj][3] += s0b + s1b;
        float2 o0 = {acc[nj][0], acc[nj][1]};
        *(float2*)&g_S[((size_t)(b*CC + c0 + row0))*QQ + q_] = o0;
        float2 o1 = {acc[nj][2], acc[nj][3]};
        *(float2*)&g_S[((size_t)(b*CC + c0 + row1))*QQ + q_] = o1;
    }

    // ---- row stats: max over q (mask qm) within this warp's 128 cols ----
    float rm0 = -INFINITY, rm1 = -INFINITY;
#pragma unroll
    for (int nj = 0; nj < 16; nj++) {
        int q_ = wn + nj*8 + tg*2;
        float ma = qmn[q_], mb = qmn[q_+1];
        rm0 = fmaxf(rm0, fmaxf(acc[nj][0]+ma, acc[nj][1]+mb));
        rm1 = fmaxf(rm1, fmaxf(acc[nj][2]+ma, acc[nj][3]+mb));
    }
#pragma unroll
    for (int o = 1; o <= 2; o <<= 1) {
        rm0 = fmaxf(rm0, __shfl_xor_sync(0xffffffffu, rm0, o));
        rm1 = fmaxf(rm1, __shfl_xor_sync(0xffffffffu, rm1, o));
    }
    if (tg == 0) {
        rmaxS[row0*2 + warp_n] = rm0;
        rmaxS[row1*2 + warp_n] = rm1;
    }

    // ---- column partial max over the 64 c in this block (mask cm) ----
    float cmk0 = cmn[row0], cmk1 = cmn[row1];
    float colm[16][2];
#pragma unroll
    for (int nj = 0; nj < 16; nj++) {
        colm[nj][0] = fmaxf(acc[nj][0]+cmk0, acc[nj][2]+cmk1);
        colm[nj][1] = fmaxf(acc[nj][1]+cmk0, acc[nj][3]+cmk1);
    }
#pragma unroll
    for (int o = 4; o <= 16; o <<= 1)
#pragma unroll
        for (int nj = 0; nj < 16; nj++) {
            colm[nj][0] = fmaxf(colm[nj][0], __shfl_xor_sync(0xffffffffu, colm[nj][0], o));
            colm[nj][1] = fmaxf(colm[nj][1], __shfl_xor_sync(0xffffffffu, colm[nj][1], o));
        }
    if (lane < 4) {
#pragma unroll
        for (int nj = 0; nj < 16; nj++) {
            int q_ = wn + nj*8 + tg*2;
            cmaxS[q_*4 + warp_m]     = colm[nj][0];
            cmaxS[(q_+1)*4 + warp_m] = colm[nj][1];
        }
    }
    __syncthreads();

    // ---- row sums with combined max ----
    float M0 = fmaxf(rmaxS[row0*2], rmaxS[row0*2+1]);
    float M1 = fmaxf(rmaxS[row1*2], rmaxS[row1*2+1]);
    float rs0 = 0.f, rs1 = 0.f;
#pragma unroll
    for (int nj = 0; nj < 16; nj++) {
        int q_ = wn + nj*8 + tg*2;
        float ma = qmn[q_], mb = qmn[q_+1];
        rs0 += __expf(acc[nj][0]+ma - M0) + __expf(acc[nj][1]+mb - M0);
        rs1 += __expf(acc[nj][2]+ma - M1) + __expf(acc[nj][3]+mb - M1);
    }
#pragma unroll
    for (int o = 1; o <= 2; o <<= 1) {
        rs0 += __shfl_xor_sync(0xffffffffu, rs0, o);
        rs1 += __shfl_xor_sync(0xffffffffu, rs1, o);
    }
    if (tg == 0) {
        rsumS[row0*2 + warp_n] = rs0;
        rsumS[row1*2 + warp_n] = rs1;
    }

    // ---- column partial sums with block-combined max ----
    float cols[16][2];
#pragma unroll
    for (int nj = 0; nj < 16; nj++) {
        int q_ = wn + nj*8 + tg*2;
        float Mc0 = fmaxf(fmaxf(cmaxS[q_*4+0], cmaxS[q_*4+1]),
                          fmaxf(cmaxS[q_*4+2], cmaxS[q_*4+3]));
        float Mc1 = fmaxf(fmaxf(cmaxS[(q_+1)*4+0], cmaxS[(q_+1)*4+1]),
                          fmaxf(cmaxS[(q_+1)*4+2], cmaxS[(q_+1)*4+3]));
        cols[nj][0] = __expf(acc[nj][0]+cmk0 - Mc0) + __expf(acc[nj][2]+cmk1 - Mc0);
        cols[nj][1] = __expf(acc[nj][1]+cmk0 - Mc1) + __expf(acc[nj][3]+cmk1 - Mc1);
    }
#pragma unroll
    for (int o = 4; o <= 16; o <<= 1)
#pragma unroll
        for (int nj = 0; nj < 16; nj++) {
            cols[nj][0] += __shfl_xor_sync(0xffffffffu, cols[nj][0], o);
            cols[nj][1] += __shfl_xor_sync(0xffffffffu, cols[nj][1], o);
        }
    if (lane < 4) {
#pragma unroll
        for (int nj = 0; nj < 16; nj++) {
            int q_ = wn + nj*8 + tg*2;
            csumS[q_*4 + warp_m]     = cols[nj][0];
            csumS[(q_+1)*4 + warp_m] = cols[nj][1];
        }
    }
    __syncthreads();

    // ---- final writes ----
    if (tid < 64) {
        g_rowM[b*CC + c0 + tid] = fmaxf(rmaxS[tid*2], rmaxS[tid*2+1]);
        g_rowZ[b*CC + c0 + tid] = rsumS[tid*2] + rsumS[tid*2+1];
    }
    {
        int q_ = tid;  // 0..255
        float m = fmaxf(fmaxf(cmaxS[q_*4+0], cmaxS[q_*4+1]),
                        fmaxf(cmaxS[q_*4+2], cmaxS[q_*4+3]));
        float s = csumS[q_*4+0] + csumS[q_*4+1] + csumS[q_*4+2] + csumS[q_*4+3];
        g_pm[(b*NCHUNK + cb)*QQ + q_] = m;
        g_ps[(b*NCHUNK + cb)*QQ + q_] = s;
    }
}

// K2c: combine the NCHUNK partial column stats
__global__ void k2c_combine()
{
    int idx = blockIdx.x * blockDim.x + threadIdx.x;
    if (idx >= BB*QQ) return;
    int b = idx / QQ, q = idx - b*QQ;
    float m = -INFINITY;
#pragma unroll
    for (int ch = 0; ch < NCHUNK; ch++)
        m = fmaxf(m, g_pm[(b*NCHUNK + ch)*QQ + q]);
    float s = 0.f;
#pragma unroll
    for (int ch = 0; ch < NCHUNK; ch++)
        s += g_ps[(b*NCHUNK + ch)*QQ + q] * __expf(g_pm[(b*NCHUNK + ch)*QQ + q] - m);
    g_colM[idx] = m;
    g_colZ[idx] = s;
}

// ---------------------------------------------------------------------------
// K3: A[b,q,d] = sum_c Pcol[c,q] * xc[c,d]  (tensor cores)
// BLK 64q x 128d, K=C in chunks of 32. warp tile 16x64.
// ---------------------------------------------------------------------------
__global__ __launch_bounds__(256) void k3_A(const float* __restrict__ xc,
                                            const float* __restrict__ cmask)
{
    __shared__ __align__(16) __nv_bfloat16 Ah[64*AS_LD], Al[64*AS_LD];
    __shared__ __align__(16) __nv_bfloat16 Bh[32*BS_LD],  Bl[32*BS_LD];
    __shared__ float cM[64], ciZ[64], cmn[32];

    int b  = blockIdx.z;
    int q0 = blockIdx.x * 64;
    int tid = threadIdx.x;
    int warp = tid >> 5, lane = tid & 31;
    int wm = (warp >> 1) * 16, wn = (warp & 1) * 64;
    if (tid < 64) {
        cM[tid]  = g_colM[b*QQ + q0 + tid];
        ciZ[tid] = 1.f / g_colZ[b*QQ + q0 + tid];
    }
    float acc[8][4] = {};

    for (int cc0 = 0; cc0 < CC; cc0 += 32) {
        if (tid < 32) cmn[tid] = NEGV * (1.f - cmask[b*CC + cc0 + tid]);
        __syncthreads();
#pragma unroll
        for (int i = 0; i < 2; i++) {
            int f = tid + i*256;
            int c = f >> 4, q4 = (f & 15) * 4;
            float4 s4 = *(const float4*)&g_S[((size_t)(b*CC + cc0 + c))*QQ + q0 + q4];
            float msk = cmn[c];
            float p0 = __expf(s4.x + msk - cM[q4+0]) * ciZ[q4+0];
            float p1 = __expf(s4.y + msk - cM[q4+1]) * ciZ[q4+1];
            float p2 = __expf(s4.z + msk - cM[q4+2]) * ciZ[q4+2];
            float p3 = __expf(s4.w + msk - cM[q4+3]) * ciZ[q4+3];
            __nv_bfloat16 h, l;
            split2(p0, h, l); Ah[(q4+0)*AS_LD + c] = h; Al[(q4+0)*AS_LD + c] = l;
            split2(p1, h, l); Ah[(q4+1)*AS_LD + c] = h; Al[(q4+1)*AS_LD + c] = l;
            split2(p2, h, l); Ah[(q4+2)*AS_LD + c] = h; Al[(q4+2)*AS_LD + c] = l;
            split2(p3, h, l); Ah[(q4+3)*AS_LD + c] = h; Al[(q4+3)*AS_LD + c] = l;
        }
#pragma unroll
        for (int i = 0; i < 4; i++) {
            int f = tid + i*256;
            int c = f >> 5, d4 = (f & 31) * 4;
            float4 v = *(const float4*)&xc[((size_t)(b*CC + cc0 + c))*DD + d4];
            __nv_bfloat16 h, l;
            split2(v.x, h, l); Bh[c*BS_LD + d4+0] = h; Bl[c*BS_LD + d4+0] = l;
            split2(v.y, h, l); Bh[c*BS_LD + d4+1] = h; Bl[c*BS_LD + d4+1] = l;
            split2(v.z, h, l); Bh[c*BS_LD + d4+2] = h; Bl[c*BS_LD + d4+2] = l;
            split2(v.w, h, l); Bh[c*BS_LD + d4+3] = h; Bl[c*BS_LD + d4+3] = l;
        }
        __syncthreads();
#pragma unroll
        for (int ks = 0; ks < 32; ks += 16) {
            unsigned ah[4], al[4];
            int arow = wm + (lane & 15);
            int acol = ks + ((lane & 16) ? 8 : 0);
            ldsm4(ah, &Ah[arow*AS_LD + acol]);
            ldsm4(al, &Al[arow*AS_LD + acol]);
            unsigned bh[8][2], bl[8][2];
            load_bfrags(bh, bl, Bh, Bl, BS_LD, ks, wn, lane);
#pragma unroll
            for (int nj = 0; nj < 8; nj++) {
                mma16816(acc[nj], ah, bh[nj]);
                mma16816(acc[nj], ah, bl[nj]);
                mma16816(acc[nj], al, bh[nj]);
            }
        }
        __syncthreads();
    }

    int g = lane >> 2, tg = lane & 3;
#pragma unroll
    for (int nj = 0; nj < 8; nj++) {
        int q_ = q0 + wm + g;
        int d_ = wn + nj*8 + tg*2;
        float2 o0 = {acc[nj][0], acc[nj][1]};
        *(float2*)&g_A[((size_t)(b*QQ + q_))*DD + d_] = o0;
        float2 o1 = {acc[nj][2], acc[nj][3]};
        *(float2*)&g_A[((size_t)(b*QQ + q_ + 8))*DD + d_] = o1;
    }
}

// ---------------------------------------------------------------------------
// K4: c2q = Prow @ xq ; q2c = Prow @ A ; write concat  (tensor cores, dual)
// BLK 64c x 128d, K=Q in chunks of 32. warp tile 16x64.
// ---------------------------------------------------------------------------
__global__ __launch_bounds__(256) void k4_out(const float* __restrict__ xc,
                                              const float* __restrict__ xq,
                                              const float* __restrict__ qmask,
                                              float* __restrict__ out)
{
    __shared__ __align__(16) __nv_bfloat16 Ah[64*AS_LD],  Al[64*AS_LD];
    __shared__ __align__(16) __nv_bfloat16 B1h[32*BS_LD], B1l[32*BS_LD];
    __shared__ __align__(16) __nv_bfloat16 B2h[32*BS_LD], B2l[32*BS_LD];
    __shared__ float rM[64], riZ[64], qmn[QQ];

    int b  = blockIdx.z;
    int c0 = blockIdx.x * 64;
    int tid = threadIdx.x;
    int warp = tid >> 5, lane = tid & 31;
    int wm = (warp >> 1) * 16, wn = (warp & 1) * 64;
    if (tid < 64) {
        rM[tid]  = g_rowM[b*CC + c0 + tid];
        riZ[tid] = 1.f / g_rowZ[b*CC + c0 + tid];
    }
    qmn[tid] = NEGV * (1.f - qmask[b*QQ + tid]);
    __syncthreads();

    float acc1[8][4] = {};
    float acc2[8][4] = {};

    for (int qq0 = 0; qq0 < QQ; qq0 += 32) {
#pragma unroll
        for (int i = 0; i < 2; i++) {
            int f = tid + i*256;
            int c = f >> 3, q4 = (f & 7) * 4;
            float4 s4 = *(const float4*)&g_S[((size_t)(b*CC + c0 + c))*QQ + qq0 + q4];
            float m = rM[c], iz = riZ[c];
            float p0 = __expf(s4.x + qmn[qq0+q4+0] - m) * iz;
            float p1 = __expf(s4.y + qmn[qq0+q4+1] - m) * iz;
            float p2 = __expf(s4.z + qmn[qq0+q4+2] - m) * iz;
            float p3 = __expf(s4.w + qmn[qq0+q4+3] - m) * iz;
            __nv_bfloat16 h, l;
            split2(p0, h, l); Ah[c*AS_LD + q4+0] = h; Al[c*AS_LD + q4+0] = l;
            split2(p1, h, l); Ah[c*AS_LD + q4+1] = h; Al[c*AS_LD + q4+1] = l;
            split2(p2, h, l); Ah[c*AS_LD + q4+2] = h; Al[c*AS_LD + q4+2] = l;
            split2(p3, h, l); Ah[c*AS_LD + q4+3] = h; Al[c*AS_LD + q4+3] = l;
        }
#pragma unroll
        for (int i = 0; i < 4; i++) {
            int f = tid + i*256;
            int q = f >> 5, d4 = (f & 31) * 4;
            float4 v = *(const float4*)&xq[((size_t)(b*QQ + qq0 + q))*DD + d4];
            __nv_bfloat16 h, l;
            split2(v.x, h, l); B1h[q*BS_LD + d4+0] = h; B1l[q*BS_LD + d4+0] = l;
            split2(v.y, h, l); B1h[q*BS_LD + d4+1] = h; B1l[q*BS_LD + d4+1] = l;
            split2(v.z, h, l); B1h[q*BS_LD + d4+2] = h; B1l[q*BS_LD + d4+2] = l;
            split2(v.w, h, l); B1h[q*BS_LD + d4+3] = h; B1l[q*BS_LD + d4+3] = l;
            float4 a4 = *(const float4*)&g_A[((size_t)(b*QQ + qq0 + q))*DD + d4];
            split2(a4.x, h, l); B2h[q*BS_LD + d4+0] = h; B2l[q*BS_LD + d4+0] = l;
            split2(a4.y, h, l); B2h[q*BS_LD + d4+1] = h; B2l[q*BS_LD + d4+1] = l;
            split2(a4.z, h, l); B2h[q*BS_LD + d4+2] = h; B2l[q*BS_LD + d4+2] = l;
            split2(a4.w, h, l); B2h[q*BS_LD + d4+3] = h; B2l[q*BS_LD + d4+3] = l;
        }
        __syncthreads();
#pragma unroll
        for (int ks = 0; ks < 32; ks += 16) {
            unsigned ah[4], al[4];
            int arow = wm + (lane & 15);
            int acol = ks + ((lane & 16) ? 8 : 0);
            ldsm4(ah, &Ah[arow*AS_LD + acol]);
            ldsm4(al, &Al[arow*AS_LD + acol]);
            unsigned bh[8][2], bl[8][2];
            load_bfrags(bh, bl, B1h, B1l, BS_LD, ks, wn, lane);
#pragma unroll
            for (int nj = 0; nj < 8; nj++) {
                mma16816(acc1[nj], ah, bh[nj]);
                mma16816(acc1[nj], ah, bl[nj]);
                mma16816(acc1[nj], al, bh[nj]);
            }
            load_bfrags(bh, bl, B2h, B2l, BS_LD, ks, wn, lane);
#pragma unroll
            for (int nj = 0; nj < 8; nj++) {
                mma16816(acc2[nj], ah, bh[nj]);
                mma16816(acc2[nj], ah, bl[nj]);
                mma16816(acc2[nj], al, bh[nj]);
            }
        }
        __syncthreads();
    }

    int g = lane >> 2, tg = lane & 3;
#pragma unroll
    for (int nj = 0; nj < 8; nj++) {
        int d_ = wn + nj*8 + tg*2;
#pragma unroll
        for (int half = 0; half < 2; half++) {
            int c_ = c0 + wm + g + half*8;
            size_t rbase = (size_t)(b*CC + c_);
            float2 xv = *(const float2*)&xc[rbase*DD + d_];
            float2 c2q = {half ? acc1[nj][2] : acc1[nj][0],
                          half ? acc1[nj][3] : acc1[nj][1]};
            float2 q2c = {half ? acc2[nj][2] : acc2[nj][0],
                          half ? acc2[nj][3] : acc2[nj][1]};
            float* ob = out + rbase*OUTD;
            *(float2*)&ob[d_] = xv;
            *(float2*)&ob[DD + d_] = c2q;
            float2 m1 = {xv.x*c2q.x, xv.y*c2q.y};
            *(float2*)&ob[2*DD + d_] = m1;
            float2 m2 = {xv.x*q2c.x, xv.y*q2c.y};
            *(float2*)&ob[3*DD + d_] = m2;
        }
    }
}

// ---------------------------------------------------------------------------
extern "C" void kernel_launch(void* const* d_in, const int* in_sizes, int n_in,
                              void* d_out, int out_size)
{
    const float* xc   = (const float*)d_in[0];
    const float* xq   = (const float*)d_in[1];
    const float* cm   = (const float*)d_in[2];
    const float* qm   = (const float*)d_in[3];
    const float* W0   = (const float*)d_in[4];
    const float* W1   = (const float*)d_in[5];
    const float* W2   = (const float*)d_in[6];
    const float* bias = (const float*)d_in[7];
    float* out = (float*)d_out;

    k_s0<<<BB*CC/8, 256>>>(xc, W0, bias);
    k_s1<<<BB*QQ/8, 256>>>(xq, W1);
    k1_S<<<dim3(1, NCHUNK, BB), 256>>>(xc, xq, W2, cm, qm);
    k2c_combine<<<BB*QQ/256, 256>>>();
    k3_A<<<dim3(QQ/64, 1, BB), 256>>>(xc, cm);
    k4_out<<<dim3(CC/64, 1, BB), 256>>>(xc, xq, qm, out);
}

// round 7
// speedup vs baseline: 1.0389x; 1.0389x over previous
#include <cuda_runtime.h>
#include <cuda_bf16.h>
#include <math.h>

#define BB 64
#define CC 1024
#define QQ 256
#define DD 128
#define OUTD (4*DD)
#define NEGV (-1e30f)
#define NCHUNK 8

// smem leading dims (bf16 elements)
#define AS_LD 40     // 32 + 8 pad
#define BS_LD 136    // 128 + 8 pad

// ---- scratch (device globals: allocation-free) ----
__device__ float g_S[(size_t)BB*CC*QQ];      // final S, 64 MB
__device__ float g_s0[BB*CC];
__device__ float g_s1[BB*QQ];
__device__ float g_pm[BB*NCHUNK*QQ];
__device__ float g_ps[BB*NCHUNK*QQ];
__device__ float g_colM[BB*QQ];
__device__ float g_colZ[BB*QQ];
__device__ float g_rowM[BB*CC];
__device__ float g_rowZ[BB*CC];
// pre-split bf16 operands (hi/lo)
__device__ __nv_bfloat16 g_Ah[(size_t)BB*QQ*DD],  g_Al[(size_t)BB*QQ*DD];
__device__ __nv_bfloat16 g_xcwh[(size_t)BB*CC*DD], g_xcwl[(size_t)BB*CC*DD];
__device__ __nv_bfloat16 g_xch[(size_t)BB*CC*DD],  g_xcl[(size_t)BB*CC*DD];
__device__ __nv_bfloat16 g_xqh[(size_t)BB*QQ*DD],  g_xql[(size_t)BB*QQ*DD];

// ---------------------------------------------------------------------------
// helpers
// ---------------------------------------------------------------------------
__device__ __forceinline__ void mma16816(float* c, const unsigned* a, const unsigned* b)
{
    asm volatile(
        "mma.sync.aligned.m16n8k16.row.col.f32.bf16.bf16.f32 "
        "{%0,%1,%2,%3},{%4,%5,%6,%7},{%8,%9},{%0,%1,%2,%3};"
        : "+f"(c[0]), "+f"(c[1]), "+f"(c[2]), "+f"(c[3])
        : "r"(a[0]), "r"(a[1]), "r"(a[2]), "r"(a[3]), "r"(b[0]), "r"(b[1]));
}

__device__ __forceinline__ void ldsm4(unsigned* r, const __nv_bfloat16* p)
{
    unsigned addr = (unsigned)__cvta_generic_to_shared(p);
    asm volatile("ldmatrix.sync.aligned.m8n8.x4.shared.b16 {%0,%1,%2,%3},[%4];"
                 : "=r"(r[0]), "=r"(r[1]), "=r"(r[2]), "=r"(r[3]) : "r"(addr));
}

__device__ __forceinline__ void ldsm4t(unsigned* r, const __nv_bfloat16* p)
{
    unsigned addr = (unsigned)__cvta_generic_to_shared(p);
    asm volatile("ldmatrix.sync.aligned.m8n8.x4.trans.shared.b16 {%0,%1,%2,%3},[%4];"
                 : "=r"(r[0]), "=r"(r[1]), "=r"(r[2]), "=r"(r[3]) : "r"(addr));
}

__device__ __forceinline__ void split2(float x, __nv_bfloat16& h, __nv_bfloat16& l)
{
    h = __float2bfloat16(x);
    l = __float2bfloat16(x - __bfloat162float(h));
}

__device__ __forceinline__ void st2(__nv_bfloat16* p, __nv_bfloat16 a, __nv_bfloat16 b)
{
    __nv_bfloat162 t; t.x = a; t.y = b;
    *(__nv_bfloat162*)p = t;
}

// B-frags from [k][n] layout via trans-ldsm (k3/k4)
__device__ __forceinline__ void load_bfrags(unsigned bh[8][2], unsigned bl[8][2],
                                            const __nv_bfloat16* Bh, const __nv_bfloat16* Bl,
                                            int ld, int ks, int wn, int lane)
{
    int brow = ks + (lane & 7) + ((lane & 16) ? 8 : 0);
#pragma unroll
    for (int g4 = 0; g4 < 4; g4++) {
        int bcol = wn + g4*16 + ((lane & 8) ? 8 : 0);
        unsigned t[4];
        ldsm4t(t, &Bh[brow*ld + bcol]);
        bh[2*g4][0] = t[0]; bh[2*g4][1] = t[2];
        bh[2*g4+1][0] = t[1]; bh[2*g4+1][1] = t[3];
        ldsm4t(t, &Bl[brow*ld + bcol]);
        bl[2*g4][0] = t[0]; bl[2*g4][1] = t[2];
        bl[2*g4+1][0] = t[1]; bl[2*g4+1][1] = t[3];
    }
}

// B-frags from [n][k] layout via non-trans ldsm (k1: natural xq layout)
__device__ __forceinline__ void load_bfrags_nk(unsigned bh[8][2], unsigned bl[8][2],
                                               const __nv_bfloat16* Bh, const __nv_bfloat16* Bl,
                                               int ld, int ks, int wn, int lane)
{
    int row = wn + ((lane & 16) ? 8 : 0) + (lane & 7);
    int col = ks + ((lane & 8) ? 8 : 0);
#pragma unroll
    for (int g2 = 0; g2 < 4; g2++) {
        unsigned t[4];
        ldsm4(t, &Bh[(row + g2*16)*ld + col]);
        bh[2*g2][0]   = t[0]; bh[2*g2][1]   = t[1];
        bh[2*g2+1][0] = t[2]; bh[2*g2+1][1] = t[3];
        ldsm4(t, &Bl[(row + g2*16)*ld + col]);
        bl[2*g2][0]   = t[0]; bl[2*g2][1]   = t[1];
        bl[2*g2+1][0] = t[2]; bl[2*g2+1][1] = t[3];
    }
}

// ---------------------------------------------------------------------------
// prep: hi/lo split of xc, xc*W2 and xq (one float4 per thread)
// ---------------------------------------------------------------------------
__global__ void kprep_xc(const float* __restrict__ xc, const float* __restrict__ W2)
{
    size_t f = ((size_t)blockIdx.x*256 + threadIdx.x) * 4;
    int d4 = (int)(f & (DD-1));
    float4 v = *(const float4*)&xc[f];
    float4 w = *(const float4*)&W2[d4];
    __nv_bfloat16 h0,l0,h1,l1,h2,l2,h3,l3;
    split2(v.x,h0,l0); split2(v.y,h1,l1); split2(v.z,h2,l2); split2(v.w,h3,l3);
    st2(&g_xch[f],h0,h1); st2(&g_xch[f+2],h2,h3);
    st2(&g_xcl[f],l0,l1); st2(&g_xcl[f+2],l2,l3);
    split2(v.x*w.x,h0,l0); split2(v.y*w.y,h1,l1);
    split2(v.z*w.z,h2,l2); split2(v.w*w.w,h3,l3);
    st2(&g_xcwh[f],h0,h1); st2(&g_xcwh[f+2],h2,h3);
    st2(&g_xcwl[f],l0,l1); st2(&g_xcwl[f+2],l2,l3);
}

__global__ void kprep_xq(const float* __restrict__ xq)
{
    size_t f = ((size_t)blockIdx.x*256 + threadIdx.x) * 4;
    float4 v = *(const float4*)&xq[f];
    __nv_bfloat16 h0,l0,h1,l1,h2,l2,h3,l3;
    split2(v.x,h0,l0); split2(v.y,h1,l1); split2(v.z,h2,l2); split2(v.w,h3,l3);
    st2(&g_xqh[f],h0,h1); st2(&g_xqh[f+2],h2,h3);
    st2(&g_xql[f],l0,l1); st2(&g_xql[f+2],l2,l3);
}

// ---------------------------------------------------------------------------
// projections
// ---------------------------------------------------------------------------
__device__ __forceinline__ float row_dot(const float* __restrict__ xr,
                                         const float* __restrict__ W, int lane)
{
    float s = 0.f;
#pragma unroll
    for (int d = 0; d < DD; d += 32) s += xr[d + lane] * W[d + lane];
#pragma unroll
    for (int o = 16; o > 0; o >>= 1) s += __shfl_xor_sync(0xffffffffu, s, o);
    return s;
}

__global__ void k_s0(const float* __restrict__ x, const float* __restrict__ W,
                     const float* __restrict__ bias)
{
    int warp = (blockIdx.x * blockDim.x + threadIdx.x) >> 5;
    int lane = threadIdx.x & 31;
    if (warp >= BB*CC) return;
    float s = row_dot(x + (size_t)warp * DD, W, lane);
    if (lane == 0) g_s0[warp] = s + bias[0];
}

__global__ void k_s1(const float* __restrict__ x, const float* __restrict__ W)
{
    int warp = (blockIdx.x * blockDim.x + threadIdx.x) >> 5;
    int lane = threadIdx.x & 31;
    if (warp >= BB*QQ) return;
    float s = row_dot(x + (size_t)warp * DD, W, lane);
    if (lane == 0) g_s1[warp] = s;
}

// ---------------------------------------------------------------------------
// K1: S = (xc*W2) @ xq^T + s0 + s1.  BLK 128c x 128q, warp tile 32x64.
// A from g_xcwh/l ([m][k]), B from g_xqh/l ([n][k] natural) -- copy fills.
// ---------------------------------------------------------------------------
__global__ __launch_bounds__(256) void k1_S(const float* __restrict__ dummy)
{
    __shared__ __align__(16) __nv_bfloat16 Ah[128*AS_LD], Al[128*AS_LD];
    __shared__ __align__(16) __nv_bfloat16 Bh[128*AS_LD], Bl[128*AS_LD];

    int b  = blockIdx.z;
    int c0 = blockIdx.y * 128;
    int q0 = blockIdx.x * 128;
    int tid = threadIdx.x;
    int warp = tid >> 5, lane = tid & 31;
    int wm = (warp >> 1) * 32, wn = (warp & 1) * 64;

    float acc[2][8][4] = {};

    for (int k0 = 0; k0 < DD; k0 += 32) {
#pragma unroll
        for (int i = 0; i < 2; i++) {
            int f = tid + i*256;
            int r = f >> 2, c8 = (f & 3) * 8;
            size_t ga = ((size_t)(b*CC + c0 + r))*DD + k0 + c8;
            *(uint4*)&Ah[r*AS_LD + c8] = *(const uint4*)&g_xcwh[ga];
            *(uint4*)&Al[r*AS_LD + c8] = *(const uint4*)&g_xcwl[ga];
            size_t gb = ((size_t)(b*QQ + q0 + r))*DD + k0 + c8;
            *(uint4*)&Bh[r*AS_LD + c8] = *(const uint4*)&g_xqh[gb];
            *(uint4*)&Bl[r*AS_LD + c8] = *(const uint4*)&g_xql[gb];
        }
        __syncthreads();
#pragma unroll
        for (int ks = 0; ks < 32; ks += 16) {
            unsigned ah[2][4], al[2][4];
            int arow = wm + (lane & 15);
            int acol = ks + ((lane & 16) ? 8 : 0);
            ldsm4(ah[0], &Ah[arow*AS_LD + acol]);
            ldsm4(ah[1], &Ah[(arow+16)*AS_LD + acol]);
            ldsm4(al[0], &Al[arow*AS_LD + acol]);
            ldsm4(al[1], &Al[(arow+16)*AS_LD + acol]);
            unsigned bh[8][2], bl[8][2];
            load_bfrags_nk(bh, bl, Bh, Bl, AS_LD, ks, wn, lane);
#pragma unroll
            for (int mi = 0; mi < 2; mi++)
#pragma unroll
                for (int nj = 0; nj < 8; nj++) {
                    mma16816(acc[mi][nj], ah[mi], bh[nj]);
                    mma16816(acc[mi][nj], ah[mi], bl[nj]);
                    mma16816(acc[mi][nj], al[mi], bh[nj]);
                }
        }
        __syncthreads();
    }

    int g = lane >> 2, tg = lane & 3;
#pragma unroll
    for (int mi = 0; mi < 2; mi++) {
#pragma unroll
        for (int nj = 0; nj < 8; nj++) {
            int c_ = c0 + wm + mi*16 + g;
            int q_ = q0 + wn + nj*8 + tg*2;
            float s0a = g_s0[b*CC + c_];
            float s0b = g_s0[b*CC + c_ + 8];
            float s1a = g_s1[b*QQ + q_], s1b = g_s1[b*QQ + q_ + 1];
            float2 o0 = {acc[mi][nj][0] + s0a + s1a, acc[mi][nj][1] + s0a + s1b};
            *(float2*)&g_S[((size_t)(b*CC + c_))*QQ + q_] = o0;
            float2 o1 = {acc[mi][nj][2] + s0b + s1a, acc[mi][nj][3] + s0b + s1b};
            *(float2*)&g_S[((size_t)(b*CC + c_ + 8))*QQ + q_] = o1;
        }
    }
}

// ---------------------------------------------------------------------------
// K2a: per-(b,q) partial max/sumexp over c (MLP-4 unrolled)
// ---------------------------------------------------------------------------
__global__ __launch_bounds__(256) void k2a_colstats(const float* __restrict__ cmask)
{
    int b = blockIdx.y;
    int chunk = blockIdx.x;
    int q = threadIdx.x;
    const float* Sp = g_S + (size_t)(b*CC)*QQ;
    const float* cm = cmask + b*CC;
    float m = -INFINITY, s = 0.f;
    int cbeg = chunk * (CC/NCHUNK);
#pragma unroll 2
    for (int c = cbeg; c < cbeg + CC/NCHUNK; c += 4) {
        float v0 = Sp[(size_t)(c+0)*QQ + q] + NEGV * (1.f - cm[c+0]);
        float v1 = Sp[(size_t)(c+1)*QQ + q] + NEGV * (1.f - cm[c+1]);
        float v2 = Sp[(size_t)(c+2)*QQ + q] + NEGV * (1.f - cm[c+2]);
        float v3 = Sp[(size_t)(c+3)*QQ + q] + NEGV * (1.f - cm[c+3]);
        float m4 = fmaxf(fmaxf(v0, v1), fmaxf(v2, v3));
        if (m4 > m) { s *= __expf(m - m4); m = m4; }
        s += __expf(v0 - m) + __expf(v1 - m) + __expf(v2 - m) + __expf(v3 - m);
    }
    g_pm[(b*NCHUNK + chunk)*QQ + q] = m;
    g_ps[(b*NCHUNK + chunk)*QQ + q] = s;
}

// K2b: per-(b,c) row max/sumexp over q
__global__ __launch_bounds__(256) void k2b_rowstats(const float* __restrict__ qmask)
{
    int row  = (blockIdx.x * blockDim.x + threadIdx.x) >> 5;
    int lane = threadIdx.x & 31;
    if (row >= BB*CC) return;
    int b = row / CC;
    const float* Sp = g_S + (size_t)row * QQ;
    const float* qm = qmask + b*QQ;
    float v[8];
    float m = -INFINITY;
#pragma unroll
    for (int j = 0; j < 8; j++) {
        v[j] = Sp[j*32 + lane] + NEGV * (1.f - qm[j*32 + lane]);
        m = fmaxf(m, v[j]);
    }
#pragma unroll
    for (int o = 16; o > 0; o >>= 1) m = fmaxf(m, __shfl_xor_sync(0xffffffffu, m, o));
    float s = 0.f;
#pragma unroll
    for (int j = 0; j < 8; j++) s += __expf(v[j] - m);
#pragma unroll
    for (int o = 16; o > 0; o >>= 1) s += __shfl_xor_sync(0xffffffffu, s, o);
    if (lane == 0) { g_rowM[row] = m; g_rowZ[row] = s; }
}

__global__ void k2c_combine()
{
    int idx = blockIdx.x * blockDim.x + threadIdx.x;
    if (idx >= BB*QQ) return;
    int b = idx / QQ, q = idx - b*QQ;
    float m = -INFINITY;
#pragma unroll
    for (int ch = 0; ch < NCHUNK; ch++)
        m = fmaxf(m, g_pm[(b*NCHUNK + ch)*QQ + q]);
    float s = 0.f;
#pragma unroll
    for (int ch = 0; ch < NCHUNK; ch++)
        s += g_ps[(b*NCHUNK + ch)*QQ + q] * __expf(g_pm[(b*NCHUNK + ch)*QQ + q] - m);
    g_colM[idx] = m;
    g_colZ[idx] = s;
}

// ---------------------------------------------------------------------------
// K3: A[b,q,d] = sum_c Pcol[c,q]*xc[c,d].  BLK 64q x 128d, warp tile 16x64.
// B from g_xch/l ([k][n] copy), A-result stored as bf16 hi/lo.
// ---------------------------------------------------------------------------
__global__ __launch_bounds__(256) void k3_A(const float* __restrict__ cmask)
{
    __shared__ __align__(16) __nv_bfloat16 Ah[64*AS_LD], Al[64*AS_LD];
    __shared__ __align__(16) __nv_bfloat16 Bh[32*BS_LD],  Bl[32*BS_LD];
    __shared__ float cM[64], ciZ[64], cmn[32];

    int b  = blockIdx.z;
    int q0 = blockIdx.x * 64;
    int tid = threadIdx.x;
    int warp = tid >> 5, lane = tid & 31;
    int wm = (warp >> 1) * 16, wn = (warp & 1) * 64;
    if (tid < 64) {
        cM[tid]  = g_colM[b*QQ + q0 + tid];
        ciZ[tid] = 1.f / g_colZ[b*QQ + q0 + tid];
    }
    float acc[8][4] = {};

    for (int cc0 = 0; cc0 < CC; cc0 += 32) {
        if (tid < 32) cmn[tid] = NEGV * (1.f - cmask[b*CC + cc0 + tid]);
        __syncthreads();
        // A tile: P^T [q 64][c 32] via expf (scatter)
#pragma unroll
        for (int i = 0; i < 2; i++) {
            int f = tid + i*256;
            int c = f >> 4, q4 = (f & 15) * 4;
            float4 s4 = *(const float4*)&g_S[((size_t)(b*CC + cc0 + c))*QQ + q0 + q4];
            float msk = cmn[c];
            float p0 = __expf(s4.x + msk - cM[q4+0]) * ciZ[q4+0];
            float p1 = __expf(s4.y + msk - cM[q4+1]) * ciZ[q4+1];
            float p2 = __expf(s4.z + msk - cM[q4+2]) * ciZ[q4+2];
            float p3 = __expf(s4.w + msk - cM[q4+3]) * ciZ[q4+3];
            __nv_bfloat16 h, l;
            split2(p0, h, l); Ah[(q4+0)*AS_LD + c] = h; Al[(q4+0)*AS_LD + c] = l;
            split2(p1, h, l); Ah[(q4+1)*AS_LD + c] = h; Al[(q4+1)*AS_LD + c] = l;
            split2(p2, h, l); Ah[(q4+2)*AS_LD + c] = h; Al[(q4+2)*AS_LD + c] = l;
            split2(p3, h, l); Ah[(q4+3)*AS_LD + c] = h; Al[(q4+3)*AS_LD + c] = l;
        }
        // B tile: copy [c 32][d 128] from prepared bf16
#pragma unroll
        for (int i = 0; i < 2; i++) {
            int f = tid + i*256;
            int c = f >> 4, d8 = (f & 15) * 8;
            size_t gb = ((size_t)(b*CC + cc0 + c))*DD + d8;
            *(uint4*)&Bh[c*BS_LD + d8] = *(const uint4*)&g_xch[gb];
            *(uint4*)&Bl[c*BS_LD + d8] = *(const uint4*)&g_xcl[gb];
        }
        __syncthreads();
#pragma unroll
        for (int ks = 0; ks < 32; ks += 16) {
            unsigned ah[4], al[4];
            int arow = wm + (lane & 15);
            int acol = ks + ((lane & 16) ? 8 : 0);
            ldsm4(ah, &Ah[arow*AS_LD + acol]);
            ldsm4(al, &Al[arow*AS_LD + acol]);
            unsigned bh[8][2], bl[8][2];
            load_bfrags(bh, bl, Bh, Bl, BS_LD, ks, wn, lane);
#pragma unroll
            for (int nj = 0; nj < 8; nj++) {
                mma16816(acc[nj], ah, bh[nj]);
                mma16816(acc[nj], ah, bl[nj]);
                mma16816(acc[nj], al, bh[nj]);
            }
        }
        __syncthreads();
    }

    int g = lane >> 2, tg = lane & 3;
#pragma unroll
    for (int nj = 0; nj < 8; nj++) {
        int q_ = q0 + wm + g;
        int d_ = wn + nj*8 + tg*2;
        __nv_bfloat16 h0, l0, h1, l1;
        split2(acc[nj][0], h0, l0); split2(acc[nj][1], h1, l1);
        st2(&g_Ah[((size_t)(b*QQ + q_))*DD + d_], h0, h1);
        st2(&g_Al[((size_t)(b*QQ + q_))*DD + d_], l0, l1);
        split2(acc[nj][2], h0, l0); split2(acc[nj][3], h1, l1);
        st2(&g_Ah[((size_t)(b*QQ + q_ + 8))*DD + d_], h0, h1);
        st2(&g_Al[((size_t)(b*QQ + q_ + 8))*DD + d_], l0, l1);
    }
}

// ---------------------------------------------------------------------------
// K4: c2q = Prow @ xq ; q2c = Prow @ A ; write concat.  BLK 64c x 128d.
// B1 from g_xqh/l, B2 from g_Ah/l -- copy fills.
// ---------------------------------------------------------------------------
__global__ __launch_bounds__(256) void k4_out(const float* __restrict__ xc,
                                              const float* __restrict__ qmask,
                                              float* __restrict__ out)
{
    __shared__ __align__(16) __nv_bfloat16 Ah[64*AS_LD],  Al[64*AS_LD];
    __shared__ __align__(16) __nv_bfloat16 B1h[32*BS_LD], B1l[32*BS_LD];
    __shared__ __align__(16) __nv_bfloat16 B2h[32*BS_LD], B2l[32*BS_LD];
    __shared__ float rM[64], riZ[64], qmn[QQ];

    int b  = blockIdx.z;
    int c0 = blockIdx.x * 64;
    int tid = threadIdx.x;
    int warp = tid >> 5, lane = tid & 31;
    int wm = (warp >> 1) * 16, wn = (warp & 1) * 64;
    if (tid < 64) {
        rM[tid]  = g_rowM[b*CC + c0 + tid];
        riZ[tid] = 1.f / g_rowZ[b*CC + c0 + tid];
    }
    qmn[tid] = NEGV * (1.f - qmask[b*QQ + tid]);
    __syncthreads();

    float acc1[8][4] = {};
    float acc2[8][4] = {};

    for (int qq0 = 0; qq0 < QQ; qq0 += 32) {
        // A tile: Prow [c 64][q 32]
#pragma unroll
        for (int i = 0; i < 2; i++) {
            int f = tid + i*256;
            int c = f >> 3, q4 = (f & 7) * 4;
            float4 s4 = *(const float4*)&g_S[((size_t)(b*CC + c0 + c))*QQ + qq0 + q4];
            float m = rM[c], iz = riZ[c];
            float p0 = __expf(s4.x + qmn[qq0+q4+0] - m) * iz;
            float p1 = __expf(s4.y + qmn[qq0+q4+1] - m) * iz;
            float p2 = __expf(s4.z + qmn[qq0+q4+2] - m) * iz;
            float p3 = __expf(s4.w + qmn[qq0+q4+3] - m) * iz;
            __nv_bfloat16 h, l;
            split2(p0, h, l); Ah[c*AS_LD + q4+0] = h; Al[c*AS_LD + q4+0] = l;
            split2(p1, h, l); Ah[c*AS_LD + q4+1] = h; Al[c*AS_LD + q4+1] = l;
            split2(p2, h, l); Ah[c*AS_LD + q4+2] = h; Al[c*AS_LD + q4+2] = l;
            split2(p3, h, l); Ah[c*AS_LD + q4+3] = h; Al[c*AS_LD + q4+3] = l;
        }
        // B tiles: copies [q 32][d 128]
#pragma unroll
        for (int i = 0; i < 2; i++) {
            int f = tid + i*256;
            int q = f >> 4, d8 = (f & 15) * 8;
            size_t gb = ((size_t)(b*QQ + qq0 + q))*DD + d8;
            *(uint4*)&B1h[q*BS_LD + d8] = *(const uint4*)&g_xqh[gb];
            *(uint4*)&B1l[q*BS_LD + d8] = *(const uint4*)&g_xql[gb];
            *(uint4*)&B2h[q*BS_LD + d8] = *(const uint4*)&g_Ah[gb];
            *(uint4*)&B2l[q*BS_LD + d8] = *(const uint4*)&g_Al[gb];
        }
        __syncthreads();
#pragma unroll
        for (int ks = 0; ks < 32; ks += 16) {
            unsigned ah[4], al[4];
            int arow = wm + (lane & 15);
            int acol = ks + ((lane & 16) ? 8 : 0);
            ldsm4(ah, &Ah[arow*AS_LD + acol]);
            ldsm4(al, &Al[arow*AS_LD + acol]);
            unsigned bh[8][2], bl[8][2];
            load_bfrags(bh, bl, B1h, B1l, BS_LD, ks, wn, lane);
#pragma unroll
            for (int nj = 0; nj < 8; nj++) {
                mma16816(acc1[nj], ah, bh[nj]);
                mma16816(acc1[nj], ah, bl[nj]);
                mma16816(acc1[nj], al, bh[nj]);
            }
            load_bfrags(bh, bl, B2h, B2l, BS_LD, ks, wn, lane);
#pragma unroll
            for (int nj = 0; nj < 8; nj++) {
                mma16816(acc2[nj], ah, bh[nj]);
                mma16816(acc2[nj], ah, bl[nj]);
                mma16816(acc2[nj], al, bh[nj]);
            }
        }
        __syncthreads();
    }

    int g = lane >> 2, tg = lane & 3;
#pragma unroll
    for (int nj = 0; nj < 8; nj++) {
        int d_ = wn + nj*8 + tg*2;
#pragma unroll
        for (int half = 0; half < 2; half++) {
            int c_ = c0 + wm + g + half*8;
            size_t rbase = (size_t)(b*CC + c_);
            float2 xv = *(const float2*)&xc[rbase*DD + d_];
            float2 c2q = {half ? acc1[nj][2] : acc1[nj][0],
                          half ? acc1[nj][3] : acc1[nj][1]};
            float2 q2c = {half ? acc2[nj][2] : acc2[nj][0],
                          half ? acc2[nj][3] : acc2[nj][1]};
            float* ob = out + rbase*OUTD;
            *(float2*)&ob[d_] = xv;
            *(float2*)&ob[DD + d_] = c2q;
            float2 m1 = {xv.x*c2q.x, xv.y*c2q.y};
            *(float2*)&ob[2*DD + d_] = m1;
            float2 m2 = {xv.x*q2c.x, xv.y*q2c.y};
            *(float2*)&ob[3*DD + d_] = m2;
        }
    }
}

// ---------------------------------------------------------------------------
extern "C" void kernel_launch(void* const* d_in, const int* in_sizes, int n_in,
                              void* d_out, int out_size)
{
    const float* xc   = (const float*)d_in[0];
    const float* xq   = (const float*)d_in[1];
    const float* cm   = (const float*)d_in[2];
    const float* qm   = (const float*)d_in[3];
    const float* W0   = (const float*)d_in[4];
    const float* W1   = (const float*)d_in[5];
    const float* W2   = (const float*)d_in[6];
    const float* bias = (const float*)d_in[7];
    float* out = (float*)d_out;

    k_s0<<<BB*CC/8, 256>>>(xc, W0, bias);
    k_s1<<<BB*QQ/8, 256>>>(xq, W1);
    kprep_xc<<<(BB*CC*DD/4)/256, 256>>>(xc, W2);
    kprep_xq<<<(BB*QQ*DD/4)/256, 256>>>(xq);
    k1_S<<<dim3(QQ/128, CC/128, BB), 256>>>(xc);
    k2a_colstats<<<dim3(NCHUNK, BB), 256>>>(cm);
    k2b_rowstats<<<BB*CC/8, 256>>>(qm);
    k2c_combine<<<BB*QQ/256, 256>>>();
    k3_A<<<dim3(QQ/64, 1, BB), 256>>>(cm);
    k4_out<<<dim3(CC/64, 1, BB), 256>>>(xc, qm, out);
}

// round 8
// speedup vs baseline: 1.1917x; 1.1471x over previous
#include <cuda_runtime.h>
#include <math.h>

#define BB 64
#define CC 1024
#define QQ 256
#define DD 128
#define OUTD (4*DD)
#define NEGV (-1e30f)
#define NCHUNK 8
#define LD 36          // f32 smem leading dim: 4*row stride mod 32 banks = 4 apart

// ---- scratch (device globals: allocation-free) ----
__device__ float g_S[(size_t)BB*CC*QQ];      // final S, 64 MB
__device__ float g_s0[BB*CC];
__device__ float g_s1[BB*QQ];
__device__ float g_pm[BB*NCHUNK*QQ];
__device__ float g_ps[BB*NCHUNK*QQ];
__device__ float g_colM[BB*QQ];
__device__ float g_colZ[BB*QQ];
__device__ float g_rowM[BB*CC];
__device__ float g_rowZ[BB*CC];
__device__ float g_AT[(size_t)BB*DD*QQ];     // (S_T @ x_cont)^T = [b][d][q], tf32-rounded
__device__ float g_xcT[(size_t)BB*DD*CC];    // xc^T [b][d][c]
__device__ float g_xqT[(size_t)BB*DD*QQ];    // xq^T [b][d][q]

// ---------------------------------------------------------------------------
// tf32 helpers
// ---------------------------------------------------------------------------
__device__ __forceinline__ float f2tf(float x)
{
    unsigned u;
    asm("cvt.rna.tf32.f32 %0, %1;" : "=r"(u) : "f"(x));
    return __uint_as_float(u);
}
__device__ __forceinline__ float4 f2tf4(float4 v)
{
    v.x = f2tf(v.x); v.y = f2tf(v.y); v.z = f2tf(v.z); v.w = f2tf(v.w);
    return v;
}

__device__ __forceinline__ void mma16808(float* c, const unsigned* a, const unsigned* b)
{
    asm volatile(
        "mma.sync.aligned.m16n8k8.row.col.f32.tf32.tf32.f32 "
        "{%0,%1,%2,%3},{%4,%5,%6,%7},{%8,%9},{%0,%1,%2,%3};"
        : "+f"(c[0]), "+f"(c[1]), "+f"(c[2]), "+f"(c[3])
        : "r"(a[0]), "r"(a[1]), "r"(a[2]), "r"(a[3]), "r"(b[0]), "r"(b[1]));
}

__device__ __forceinline__ void ldsm4f(unsigned* r, const float* p)
{
    unsigned addr = (unsigned)__cvta_generic_to_shared(p);
    asm volatile("ldmatrix.sync.aligned.m8n8.x4.shared.b16 {%0,%1,%2,%3},[%4];"
                 : "=r"(r[0]), "=r"(r[1]), "=r"(r[2]), "=r"(r[3]) : "r"(addr));
}

// A fragment (m16 x k8) from [m][k] f32 tile: regs a0..a3 in mma order
__device__ __forceinline__ void ldfragA(unsigned a[4], const float* tile,
                                        int row0, int ks, int lane)
{
    int m = lane >> 3;
    const float* p = tile + (row0 + ((m & 1) << 3) + (lane & 7))*LD
                          + ks + ((m >> 1) << 2);
    ldsm4f(a, p);
}

// B fragments for TWO adjacent n8-tiles (n-major [n][k] f32 tile):
// bq[0],bq[1] = tile nj ; bq[2],bq[3] = tile nj+1
__device__ __forceinline__ void ldfragB2(unsigned bq[4], const float* tile,
                                         int nrow0, int ks, int lane)
{
    int m = lane >> 3;
    const float* p = tile + (nrow0 + ((m >> 1) << 3) + (lane & 7))*LD
                          + ks + ((m & 1) << 2);
    ldsm4f(bq, p);
}

// ---------------------------------------------------------------------------
// transpose: src[b][R][C] -> dst[b][C][R]
// ---------------------------------------------------------------------------
__global__ void ktrans(const float* __restrict__ src, float* __restrict__ dst,
                       int R, int C)
{
    __shared__ float t[32][33];
    int b  = blockIdx.z;
    int r0 = blockIdx.y * 32, c0 = blockIdx.x * 32;
    int x = threadIdx.x, y = threadIdx.y;
#pragma unroll
    for (int i = 0; i < 32; i += 8)
        t[y+i][x] = src[((size_t)b*R + r0+y+i)*C + c0+x];
    __syncthreads();
#pragma unroll
    for (int i = 0; i < 32; i += 8)
        dst[((size_t)b*C + c0+y+i)*R + r0+x] = t[x][y+i];
}

// ---------------------------------------------------------------------------
// projections
// ---------------------------------------------------------------------------
__device__ __forceinline__ float row_dot(const float* __restrict__ xr,
                                         const float* __restrict__ W, int lane)
{
    float s = 0.f;
#pragma unroll
    for (int d = 0; d < DD; d += 32) s += xr[d + lane] * W[d + lane];
#pragma unroll
    for (int o = 16; o > 0; o >>= 1) s += __shfl_xor_sync(0xffffffffu, s, o);
    return s;
}

__global__ void k_s0(const float* __restrict__ x, const float* __restrict__ W,
                     const float* __restrict__ bias)
{
    int warp = (blockIdx.x * blockDim.x + threadIdx.x) >> 5;
    int lane = threadIdx.x & 31;
    if (warp >= BB*CC) return;
    float s = row_dot(x + (size_t)warp * DD, W, lane);
    if (lane == 0) g_s0[warp] = s + bias[0];
}

__global__ void k_s1(const float* __restrict__ x, const float* __restrict__ W)
{
    int warp = (blockIdx.x * blockDim.x + threadIdx.x) >> 5;
    int lane = threadIdx.x & 31;
    if (warp >= BB*QQ) return;
    float s = row_dot(x + (size_t)warp * DD, W, lane);
    if (lane == 0) g_s1[warp] = s;
}

// ---------------------------------------------------------------------------
// K1: S = (xc*W2) @ xq^T + s0 + s1.  tf32. BLK 128c x 128q, warp 32x64.
// A = xc*W2 [c][d] (m-major), B = xq [q][d] (n-major) -- both natural layouts.
// ---------------------------------------------------------------------------
__global__ __launch_bounds__(256) void k1_S(const float* __restrict__ xc,
                                            const float* __restrict__ xq,
                                            const float* __restrict__ W2)
{
    __shared__ __align__(16) float As[128*LD];
    __shared__ __align__(16) float Bs[128*LD];
    __shared__ float W2s[DD];

    int b  = blockIdx.z;
    int c0 = blockIdx.y * 128;
    int q0 = blockIdx.x * 128;
    int tid = threadIdx.x;
    int warp = tid >> 5, lane = tid & 31;
    int wm = (warp >> 1) * 32, wn = (warp & 1) * 64;
    if (tid < DD) W2s[tid] = W2[tid];

    float acc[2][8][4] = {};
    __syncthreads();

    for (int k0 = 0; k0 < DD; k0 += 32) {
#pragma unroll
        for (int i = 0; i < 4; i++) {
            int f = tid + i*256;
            int r = f >> 3, d4 = (f & 7) * 4;
            float4 v = *(const float4*)&xc[((size_t)(b*CC + c0 + r))*DD + k0 + d4];
            v.x *= W2s[k0+d4+0]; v.y *= W2s[k0+d4+1];
            v.z *= W2s[k0+d4+2]; v.w *= W2s[k0+d4+3];
            *(float4*)&As[r*LD + d4] = f2tf4(v);
            float4 u = *(const float4*)&xq[((size_t)(b*QQ + q0 + r))*DD + k0 + d4];
            *(float4*)&Bs[r*LD + d4] = f2tf4(u);
        }
        __syncthreads();
#pragma unroll
        for (int ks = 0; ks < 32; ks += 8) {
            unsigned a0[4], a1[4];
            ldfragA(a0, As, wm,      ks, lane);
            ldfragA(a1, As, wm + 16, ks, lane);
#pragma unroll
            for (int np = 0; np < 4; np++) {
                unsigned bq[4];
                ldfragB2(bq, Bs, wn + np*16, ks, lane);
                mma16808(acc[0][np*2],   a0, bq);
                mma16808(acc[0][np*2+1], a0, bq+2);
                mma16808(acc[1][np*2],   a1, bq);
                mma16808(acc[1][np*2+1], a1, bq+2);
            }
        }
        __syncthreads();
    }

    int g = lane >> 2, tg = lane & 3;
#pragma unroll
    for (int mi = 0; mi < 2; mi++) {
#pragma unroll
        for (int nj = 0; nj < 8; nj++) {
            int c_ = c0 + wm + mi*16 + g;
            int q_ = q0 + wn + nj*8 + tg*2;
            float s0a = g_s0[b*CC + c_];
            float s0b = g_s0[b*CC + c_ + 8];
            float s1a = g_s1[b*QQ + q_], s1b = g_s1[b*QQ + q_ + 1];
            float2 o0 = {acc[mi][nj][0] + s0a + s1a, acc[mi][nj][1] + s0a + s1b};
            *(float2*)&g_S[((size_t)(b*CC + c_))*QQ + q_] = o0;
            float2 o1 = {acc[mi][nj][2] + s0b + s1a, acc[mi][nj][3] + s0b + s1b};
            *(float2*)&g_S[((size_t)(b*CC + c_ + 8))*QQ + q_] = o1;
        }
    }
}

// ---------------------------------------------------------------------------
// K2a: per-(b,q) partial max/sumexp over c (MLP-4)
// ---------------------------------------------------------------------------
__global__ __launch_bounds__(256) void k2a_colstats(const float* __restrict__ cmask)
{
    int b = blockIdx.y;
    int chunk = blockIdx.x;
    int q = threadIdx.x;
    const float* Sp = g_S + (size_t)(b*CC)*QQ;
    const float* cm = cmask + b*CC;
    float m = -INFINITY, s = 0.f;
    int cbeg = chunk * (CC/NCHUNK);
#pragma unroll 2
    for (int c = cbeg; c < cbeg + CC/NCHUNK; c += 4) {
        float v0 = Sp[(size_t)(c+0)*QQ + q] + NEGV * (1.f - cm[c+0]);
        float v1 = Sp[(size_t)(c+1)*QQ + q] + NEGV * (1.f - cm[c+1]);
        float v2 = Sp[(size_t)(c+2)*QQ + q] + NEGV * (1.f - cm[c+2]);
        float v3 = Sp[(size_t)(c+3)*QQ + q] + NEGV * (1.f - cm[c+3]);
        float m4 = fmaxf(fmaxf(v0, v1), fmaxf(v2, v3));
        if (m4 > m) { s *= __expf(m - m4); m = m4; }
        s += __expf(v0 - m) + __expf(v1 - m) + __expf(v2 - m) + __expf(v3 - m);
    }
    g_pm[(b*NCHUNK + chunk)*QQ + q] = m;
    g_ps[(b*NCHUNK + chunk)*QQ + q] = s;
}

// K2b: per-(b,c) row max/sumexp over q
__global__ __launch_bounds__(256) void k2b_rowstats(const float* __restrict__ qmask)
{
    int row  = (blockIdx.x * blockDim.x + threadIdx.x) >> 5;
    int lane = threadIdx.x & 31;
    if (row >= BB*CC) return;
    int b = row / CC;
    const float* Sp = g_S + (size_t)row * QQ;
    const float* qm = qmask + b*QQ;
    float v[8];
    float m = -INFINITY;
#pragma unroll
    for (int j = 0; j < 8; j++) {
        v[j] = Sp[j*32 + lane] + NEGV * (1.f - qm[j*32 + lane]);
        m = fmaxf(m, v[j]);
    }
#pragma unroll
    for (int o = 16; o > 0; o >>= 1) m = fmaxf(m, __shfl_xor_sync(0xffffffffu, m, o));
    float s = 0.f;
#pragma unroll
    for (int j = 0; j < 8; j++) s += __expf(v[j] - m);
#pragma unroll
    for (int o = 16; o > 0; o >>= 1) s += __shfl_xor_sync(0xffffffffu, s, o);
    if (lane == 0) { g_rowM[row] = m; g_rowZ[row] = s; }
}

__global__ void k2c_combine()
{
    int idx = blockIdx.x * blockDim.x + threadIdx.x;
    if (idx >= BB*QQ) return;
    int b = idx / QQ, q = idx - b*QQ;
    float m = -INFINITY;
#pragma unroll
    for (int ch = 0; ch < NCHUNK; ch++)
        m = fmaxf(m, g_pm[(b*NCHUNK + ch)*QQ + q]);
    float s = 0.f;
#pragma unroll
    for (int ch = 0; ch < NCHUNK; ch++)
        s += g_ps[(b*NCHUNK + ch)*QQ + q] * __expf(g_pm[(b*NCHUNK + ch)*QQ + q] - m);
    g_colM[idx] = m;
    g_colZ[idx] = s;
}

// ---------------------------------------------------------------------------
// K3: AT[d][q] = sum_c xcT[d][c] * Pcol[c][q].  tf32.
// BLK 128d x 64q, warp 32x32. A = xcT (m-major copy), B = P^T (expf fill).
// Output written tf32-rounded so k4's B2 is a plain copy.
// ---------------------------------------------------------------------------
__global__ __launch_bounds__(256) void k3_A(const float* __restrict__ cmask)
{
    __shared__ __align__(16) float As[128*LD];   // xcT [d 128][c 32]
    __shared__ __align__(16) float Bs[64*LD];    // P^T [q 64][c 32]
    __shared__ float cM[64], ciZ[64], cmn[32];

    int b  = blockIdx.z;
    int q0 = blockIdx.x * 64;
    int tid = threadIdx.x;
    int warp = tid >> 5, lane = tid & 31;
    int wm = (warp >> 1) * 32, wn = (warp & 1) * 32;
    if (tid < 64) {
        cM[tid]  = g_colM[b*QQ + q0 + tid];
        ciZ[tid] = 1.f / g_colZ[b*QQ + q0 + tid];
    }
    float acc[2][4][4] = {};

    for (int cc0 = 0; cc0 < CC; cc0 += 32) {
        if (tid < 32) cmn[tid] = NEGV * (1.f - cmask[b*CC + cc0 + tid]);
        __syncthreads();
        // A tile: copy xcT [d][c]
#pragma unroll
        for (int i = 0; i < 4; i++) {
            int f = tid + i*256;
            int d = f >> 3, c4 = (f & 7) * 4;
            float4 v = *(const float4*)&g_xcT[((size_t)(b*DD + d))*CC + cc0 + c4];
            *(float4*)&As[d*LD + c4] = f2tf4(v);
        }
        // B tile: P^T [q][c] via expf (transpose scatter)
#pragma unroll
        for (int i = 0; i < 2; i++) {
            int f = tid + i*256;
            int c = f >> 4, q4 = (f & 15) * 4;
            float4 s4 = *(const float4*)&g_S[((size_t)(b*CC + cc0 + c))*QQ + q0 + q4];
            float msk = cmn[c];
            Bs[(q4+0)*LD + c] = f2tf(__expf(s4.x + msk - cM[q4+0]) * ciZ[q4+0]);
            Bs[(q4+1)*LD + c] = f2tf(__expf(s4.y + msk - cM[q4+1]) * ciZ[q4+1]);
            Bs[(q4+2)*LD + c] = f2tf(__expf(s4.z + msk - cM[q4+2]) * ciZ[q4+2]);
            Bs[(q4+3)*LD + c] = f2tf(__expf(s4.w + msk - cM[q4+3]) * ciZ[q4+3]);
        }
        __syncthreads();
#pragma unroll
        for (int ks = 0; ks < 32; ks += 8) {
            unsigned a0[4], a1[4];
            ldfragA(a0, As, wm,      ks, lane);
            ldfragA(a1, As, wm + 16, ks, lane);
#pragma unroll
            for (int np = 0; np < 2; np++) {
                unsigned bq[4];
                ldfragB2(bq, Bs, wn + np*16, ks, lane);
                mma16808(acc[0][np*2],   a0, bq);
                mma16808(acc[0][np*2+1], a0, bq+2);
                mma16808(acc[1][np*2],   a1, bq);
                mma16808(acc[1][np*2+1], a1, bq+2);
            }
        }
        __syncthreads();
    }

    int g = lane >> 2, tg = lane & 3;
#pragma unroll
    for (int mi = 0; mi < 2; mi++) {
#pragma unroll
        for (int nj = 0; nj < 4; nj++) {
            int d_ = wm + mi*16 + g;
            int q_ = q0 + wn + nj*8 + tg*2;
            float2 o0 = {f2tf(acc[mi][nj][0]), f2tf(acc[mi][nj][1])};
            *(float2*)&g_AT[((size_t)(b*DD + d_))*QQ + q_] = o0;
            float2 o1 = {f2tf(acc[mi][nj][2]), f2tf(acc[mi][nj][3])};
            *(float2*)&g_AT[((size_t)(b*DD + d_ + 8))*QQ + q_] = o1;
        }
    }
}

// ---------------------------------------------------------------------------
// K4: c2q = Prow @ xq ; q2c = Prow @ A ; write concat.  tf32, dual B.
// BLK 64c x 128d, warp 16x64. B1 = xqT [d][q], B2 = AT [d][q] (n-major).
// ---------------------------------------------------------------------------
__global__ __launch_bounds__(256) void k4_out(const float* __restrict__ xc,
                                              const float* __restrict__ qmask,
                                              float* __restrict__ out)
{
    __shared__ __align__(16) float As[64*LD];
    __shared__ __align__(16) float B1s[128*LD];
    __shared__ __align__(16) float B2s[128*LD];
    __shared__ float rM[64], riZ[64], qmn[QQ];

    int b  = blockIdx.z;
    int c0 = blockIdx.x * 64;
    int tid = threadIdx.x;
    int warp = tid >> 5, lane = tid & 31;
    int wm = (warp >> 1) * 16, wn = (warp & 1) * 64;
    if (tid < 64) {
        rM[tid]  = g_rowM[b*CC + c0 + tid];
        riZ[tid] = 1.f / g_rowZ[b*CC + c0 + tid];
    }
    qmn[tid] = NEGV * (1.f - qmask[b*QQ + tid]);
    __syncthreads();

    float acc1[8][4] = {};
    float acc2[8][4] = {};

    for (int qq0 = 0; qq0 < QQ; qq0 += 32) {
        // A tile: Prow [c 64][q 32] (aligned rows, no transpose)
#pragma unroll
        for (int i = 0; i < 2; i++) {
            int f = tid + i*256;
            int c = f >> 3, q4 = (f & 7) * 4;
            float4 s4 = *(const float4*)&g_S[((size_t)(b*CC + c0 + c))*QQ + qq0 + q4];
            float m = rM[c], iz = riZ[c];
            float4 p;
            p.x = f2tf(__expf(s4.x + qmn[qq0+q4+0] - m) * iz);
            p.y = f2tf(__expf(s4.y + qmn[qq0+q4+1] - m) * iz);
            p.z = f2tf(__expf(s4.z + qmn[qq0+q4+2] - m) * iz);
            p.w = f2tf(__expf(s4.w + qmn[qq0+q4+3] - m) * iz);
            *(float4*)&As[c*LD + q4] = p;
        }
        // B tiles: [d 128][q 32] copies from xqT / AT
#pragma unroll
        for (int i = 0; i < 4; i++) {
            int f = tid + i*256;
            int d = f >> 3, q4 = (f & 7) * 4;
            size_t gb = ((size_t)(b*DD + d))*QQ + qq0 + q4;
            float4 v = *(const float4*)&g_xqT[gb];
            *(float4*)&B1s[d*LD + q4] = f2tf4(v);
            *(float4*)&B2s[d*LD + q4] = *(const float4*)&g_AT[gb];  // pre-rounded
        }
        __syncthreads();
#pragma unroll
        for (int ks = 0; ks < 32; ks += 8) {
            unsigned a[4];
            ldfragA(a, As, wm, ks, lane);
#pragma unroll
            for (int np = 0; np < 4; np++) {
                unsigned bq[4];
                ldfragB2(bq, B1s, wn + np*16, ks, lane);
                mma16808(acc1[np*2],   a, bq);
                mma16808(acc1[np*2+1], a, bq+2);
                ldfragB2(bq, B2s, wn + np*16, ks, lane);
                mma16808(acc2[np*2],   a, bq);
                mma16808(acc2[np*2+1], a, bq+2);
            }
        }
        __syncthreads();
    }

    int g = lane >> 2, tg = lane & 3;
#pragma unroll
    for (int nj = 0; nj < 8; nj++) {
        int d_ = wn + nj*8 + tg*2;
#pragma unroll
        for (int half = 0; half < 2; half++) {
            int c_ = c0 + wm + g + half*8;
            size_t rbase = (size_t)(b*CC + c_);
            float2 xv = *(const float2*)&xc[rbase*DD + d_];
            float2 c2q = {half ? acc1[nj][2] : acc1[nj][0],
                          half ? acc1[nj][3] : acc1[nj][1]};
            float2 q2c = {half ? acc2[nj][2] : acc2[nj][0],
                          half ? acc2[nj][3] : acc2[nj][1]};
            float* ob = out + rbase*OUTD;
            *(float2*)&ob[d_] = xv;
            *(float2*)&ob[DD + d_] = c2q;
            float2 m1 = {xv.x*c2q.x, xv.y*c2q.y};
            *(float2*)&ob[2*DD + d_] = m1;
            float2 m2 = {xv.x*q2c.x, xv.y*q2c.y};
            *(float2*)&ob[3*DD + d_] = m2;
        }
    }
}

// ---------------------------------------------------------------------------
extern "C" void kernel_launch(void* const* d_in, const int* in_sizes, int n_in,
                              void* d_out, int out_size)
{
    const float* xc   = (const float*)d_in[0];
    const float* xq   = (const float*)d_in[1];
    const float* cm   = (const float*)d_in[2];
    const float* qm   = (const float*)d_in[3];
    const float* W0   = (const float*)d_in[4];
    const float* W1   = (const float*)d_in[5];
    const float* W2   = (const float*)d_in[6];
    const float* bias = (const float*)d_in[7];
    float* out = (float*)d_out;

    k_s0<<<BB*CC/8, 256>>>(xc, W0, bias);
    k_s1<<<BB*QQ/8, 256>>>(xq, W1);
    {
        float* xcT; cudaGetSymbolAddress((void**)&xcT, g_xcT);
        float* xqT; cudaGetSymbolAddress((void**)&xqT, g_xqT);
        ktrans<<<dim3(DD/32, CC/32, BB), dim3(32,8)>>>(xc, xcT, CC, DD);
        ktrans<<<dim3(DD/32, QQ/32, BB), dim3(32,8)>>>(xq, xqT, QQ, DD);
    }
    k1_S<<<dim3(QQ/128, CC/128, BB), 256>>>(xc, xq, W2);
    k2a_colstats<<<dim3(NCHUNK, BB), 256>>>(cm);
    k2b_rowstats<<<BB*CC/8, 256>>>(qm);
    k2c_combine<<<BB*QQ/256, 256>>>();
    k3_A<<<dim3(QQ/64, 1, BB), 256>>>(cm);
    k4_out<<<dim3(CC/64, 1, BB), 256>>>(xc, qm, out);
}